// round 16
// baseline (speedup 1.0000x reference)
#include <cuda_runtime.h>
#include <cstdint>

// ---------------- problem constants ----------------
#define BATCH 8
#define C_IN 256
#define LEN 2048
#define D_INNER 512
#define DT_RANK 16
#define D_STATE 16
#define NROWS (BATCH * LEN)          // 16384
#define NCHUNK 16
#define CLEN (LEN / NCHUNK)          // 128

// ---------------- scratch buffers ----------------
__device__ float g_x[NROWS * C_IN];
__device__ float g_xz[NROWS * 1024];
__device__ float g_xc[NROWS * D_INNER];
__device__ float g_xdb[NROWS * 48];
__device__ float g_delta[NROWS * D_INNER];
__device__ float g_y[NROWS * D_INNER];
__device__ float g_esum[BATCH * NCHUNK * D_INNER * D_STATE];
__device__ float g_hend[BATCH * NCHUNK * D_INNER * D_STATE];
__device__ float g_hpre[BATCH * NCHUNK * D_INNER * D_STATE];
// tf32-rounded weight copies: in_proj(2x262144) | out_proj(2x131072) | out_lin(131072)
__device__ float g_wt[2 * 262144 + 2 * 131072 + 131072];

// ---------------- helpers ----------------
__device__ __forceinline__ uint32_t cvt_tf32(float x) {
    uint32_t y;
    asm("cvt.rna.tf32.f32 %0, %1;" : "=r"(y) : "f"(x));
    return y;
}
__device__ __forceinline__ float tf32_rna(float x) {
    return __uint_as_float(cvt_tf32(x));
}
__device__ __forceinline__ float silu_f(float v) {
    return v / (1.f + __expf(-v));
}
__device__ __forceinline__ float softplus_f(float v) {
    return fmaxf(v, 0.f) + log1pf(__expf(-fabsf(v)));
}

#define CP16(dst, src) \
    asm volatile("cp.async.cg.shared.global [%0], [%1], 16;\n" :: "r"(dst), "l"(src))

__device__ __forceinline__ void ldsm_x4(uint32_t& d0, uint32_t& d1,
                                        uint32_t& d2, uint32_t& d3, uint32_t addr) {
    asm volatile("ldmatrix.sync.aligned.m8n8.x4.shared.b16 {%0,%1,%2,%3}, [%4];"
                 : "=r"(d0), "=r"(d1), "=r"(d2), "=r"(d3) : "r"(addr));
}

// ============================================================================
// Pipelined tf32 GEMM — proven mainloop; bottom sync removed (validated).
// EPI: 0 = none, 2 = bias+relu, 3 = bias+relu+SCATTER to (2,B,256,L).
// ============================================================================
template<int EPI, bool ROUND_OUT>
__global__ __launch_bounds__(256, 2)
void gemm_pipe_kernel(const float* __restrict__ A, int lda,
                      const float* __restrict__ W,
                      const float* __restrict__ bias,
                      float* __restrict__ C, int ldc, int K)
{
    extern __shared__ float smem[];
    constexpr int STAGE_FLOATS = 8192;

    const int tid  = threadIdx.x;
    const int warp = tid >> 5, lane = tid & 31;
    const int wm = warp >> 2, wn = warp & 3;
    const int g = lane >> 2, tq = lane & 3;
    const int row0 = blockIdx.y * 128;
    const int col0 = blockIdx.x * 128;

    const int arow = tid >> 3;
    const int aj   = tid & 7;
    const uint32_t swz = (uint32_t)((aj ^ (arow & 7)) << 4);
    uint32_t sbase = (uint32_t)__cvta_generic_to_shared(smem);

    const float* gA0 = A + (size_t)(row0 + arow) * lda + aj * 4;
    const float* gB0 = W + (size_t)(col0 + arow) * K   + aj * 4;

    auto load_stage = [&](int kt, int s) {
        const float* ga = gA0 + kt * 32;
        const float* gb = gB0 + kt * 32;
        uint32_t da = sbase + (uint32_t)(s * STAGE_FLOATS + arow * 32) * 4 + swz;
        uint32_t db = da + 4096 * 4;
        #pragma unroll
        for (int p = 0; p < 4; p++) {
            CP16(da + p * 4096, ga + (size_t)p * 32 * lda);
            CP16(db + p * 4096, gb + (size_t)p * 32 * K);
        }
        asm volatile("cp.async.commit_group;\n");
    };

    const int lmat = lane >> 3, lr = lane & 7;
    const uint32_t rsw = (uint32_t)lr << 4;
    uint32_t aBase[4], bBase[2];
    #pragma unroll
    for (int mt = 0; mt < 4; mt++) {
        const int row = wm * 64 + mt * 16 + (lmat & 1) * 8 + lr;
        aBase[mt] = sbase + (uint32_t)row * 128;
    }
    const uint32_t ablk = (uint32_t)(lmat >> 1);
    #pragma unroll
    for (int nt2 = 0; nt2 < 2; nt2++) {
        const int row = wn * 32 + nt2 * 16 + (lmat >> 1) * 8 + lr;
        bBase[nt2] = sbase + 4096 * 4 + (uint32_t)row * 128;
    }
    const uint32_t bblk = (uint32_t)(lmat & 1);

    float acc[4][4][4];
    #pragma unroll
    for (int mt = 0; mt < 4; mt++)
        #pragma unroll
        for (int nt = 0; nt < 4; nt++)
            #pragma unroll
            for (int i = 0; i < 4; i++) acc[mt][nt][i] = 0.f;

    const int ktiles = K / 32;
    load_stage(0, 0);
    if (ktiles > 1) load_stage(1, 1);

    int scur = 0;
    for (int kt = 0; kt < ktiles; kt++) {
        if (kt < ktiles - 1) asm volatile("cp.async.wait_group 1;\n");
        else                 asm volatile("cp.async.wait_group 0;\n");
        __syncthreads();

        if (kt + 2 < ktiles) load_stage(kt + 2, (scur + 2) % 3);

        const uint32_t soff = (uint32_t)(scur * STAGE_FLOATS) * 4;

        #pragma unroll
        for (int kk = 0; kk < 4; kk++) {
            uint32_t a[4][4], b[4][2];
            #pragma unroll
            for (int mt = 0; mt < 4; mt++) {
                const uint32_t addr = aBase[mt] + soff +
                    ((((uint32_t)(2 * kk) + ablk) << 4) ^ rsw);
                ldsm_x4(a[mt][0], a[mt][1], a[mt][2], a[mt][3], addr);
            }
            #pragma unroll
            for (int nt2 = 0; nt2 < 2; nt2++) {
                const uint32_t addr = bBase[nt2] + soff +
                    ((((uint32_t)(2 * kk) + bblk) << 4) ^ rsw);
                ldsm_x4(b[2 * nt2][0], b[2 * nt2][1],
                        b[2 * nt2 + 1][0], b[2 * nt2 + 1][1], addr);
            }
            #pragma unroll
            for (int mt = 0; mt < 4; mt++)
                #pragma unroll
                for (int nt = 0; nt < 4; nt++) {
                    asm volatile(
                        "mma.sync.aligned.m16n8k8.row.col.f32.tf32.tf32.f32 "
                        "{%0,%1,%2,%3}, {%4,%5,%6,%7}, {%8,%9}, {%0,%1,%2,%3};"
                        : "+f"(acc[mt][nt][0]), "+f"(acc[mt][nt][1]),
                          "+f"(acc[mt][nt][2]), "+f"(acc[mt][nt][3])
                        : "r"(a[mt][0]), "r"(a[mt][1]), "r"(a[mt][2]), "r"(a[mt][3]),
                          "r"(b[nt][0]), "r"(b[nt][1]));
                }
        }
        scur = (scur == 2) ? 0 : scur + 1;
    }

    #pragma unroll
    for (int mt = 0; mt < 4; mt++) {
        const int r = row0 + wm * 64 + mt * 16 + g;
        #pragma unroll
        for (int nt = 0; nt < 4; nt++) {
            const int c = col0 + wn * 32 + nt * 8 + 2 * tq;
            float b0 = 0.f, b1 = 0.f;
            if (EPI >= 2) { b0 = bias[c]; b1 = bias[c + 1]; }
            float2 v0, v1;
            v0.x = acc[mt][nt][0]; v0.y = acc[mt][nt][1];
            v1.x = acc[mt][nt][2]; v1.y = acc[mt][nt][3];
            if (EPI >= 2) {
                v0.x = fmaxf(v0.x + b0, 0.f); v0.y = fmaxf(v0.y + b1, 0.f);
                v1.x = fmaxf(v1.x + b0, 0.f); v1.y = fmaxf(v1.y + b1, 0.f);
            }
            if (ROUND_OUT) {
                v0.x = tf32_rna(v0.x); v0.y = tf32_rna(v0.y);
                v1.x = tf32_rna(v1.x); v1.y = tf32_rna(v1.y);
            }
            if (EPI == 3) {
                const int bb = r >> 11;
                const int l  = r & 2047;
                const int c1 = c + 1;
                const size_t base0 = ((size_t)((c  >> 8) * BATCH + bb)) * (C_IN * LEN)
                                   + (size_t)(c  & 255) * LEN;
                const size_t base1 = ((size_t)((c1 >> 8) * BATCH + bb)) * (C_IN * LEN)
                                   + (size_t)(c1 & 255) * LEN;
                C[base0 + l]     = v0.x;
                C[base1 + l]     = v0.y;
                C[base0 + l + 8] = v1.x;
                C[base1 + l + 8] = v1.y;
            } else {
                *(float2*)&C[(size_t)r * ldc + c] = v0;
                *(float2*)&C[(size_t)(r + 8) * ldc + c] = v1;
            }
        }
    }
}

// ---------------- tf32 rounding copy: all three weight tensors in one launch ----
__global__ __launch_bounds__(256)
void cvt_all_kernel(const float* __restrict__ w_in, const float* __restrict__ w_out,
                    const float* __restrict__ w_lin, float* __restrict__ dst)
{
    const int i = (blockIdx.x * 256 + threadIdx.x) * 4;   // over 917504 floats
    const float* src;
    int off;
    if (i < 524288)       { src = w_in;  off = i; }
    else if (i < 786432)  { src = w_out; off = i - 524288; }
    else                  { src = w_lin; off = i - 786432; }
    float4 v = *(const float4*)(src + off);
    v.x = tf32_rna(v.x); v.y = tf32_rna(v.y);
    v.z = tf32_rna(v.z); v.w = tf32_rna(v.w);
    *(float4*)(dst + i) = v;
}

// ============================================================================
// FUSED x_proj + dt_proj.  BM=64, BN=64, grid (1, 256) — each CTA owns all 48
// output columns for its 64 rows.  Mainloop = proven gemm_tf32 (BM=64,BK=32).
// Epilogue: cols 16..47 (B|C) -> global xdb;  cols 0..15 (dt) -> smem sdt.
// Then: verbatim proven dtproj body reading sdt (same values => bit-exact),
// writing delta for these 64 rows.
// Dynamic smem layout (floats): As[64*36] | Bs[64*36] | sw[8192] | sb[512] | sdt[64*16]
// ============================================================================
__global__ __launch_bounds__(256)
void xproj_dtproj_kernel(const float* __restrict__ A, int lda,
                         const float* __restrict__ W,
                         const float* __restrict__ w_dt,
                         const float* __restrict__ b_dt,
                         float* __restrict__ xdb,
                         float* __restrict__ delta,
                         int N, int K)
{
    extern __shared__ float dsm[];
    float* As  = dsm;                    // 64*36
    float* Bs  = As + 64 * 36;           // 64*36
    float* sw  = Bs + 64 * 36;           // 8192
    float* sb  = sw + 8192;              // 512
    float* sdt = sb + 512;               // 64*16

    constexpr int BM = 64, BK = 32, BKp = 36;
    constexpr int WCOLS = 4, NT = 2;     // 8 warps: 2 x 4, warp tile 32x16

    const int tid  = threadIdx.x;
    const int warp = tid >> 5, lane = tid & 31;
    const int wm = warp / WCOLS, wn = warp % WCOLS;
    const int g = lane >> 2, tq = lane & 3;
    const int row0 = blockIdx.y * BM;

    // ---- load dt_proj weights/bias into smem (disjoint region; no sync needed yet)
    #pragma unroll
    for (int i = 0; i < 8; i++)
        *(float4*)&sw[(i * 256 + tid) * 4] = *(const float4*)(w_dt + (i * 256 + tid) * 4);
    sb[tid] = b_dt[tid];
    sb[tid + 256] = b_dt[tid + 256];

    constexpr int AF4   = BK / 4;        // 8
    constexpr int ARPP  = 256 / AF4;     // 32
    constexpr int APASS = BM / ARPP;     // 2
    constexpr int BPASS = BM / ARPP;     // 2 (BN=64)
    const int ar = tid / AF4;
    const int aq = tid % AF4;

    float4 pa[APASS], pb[BPASS];
    const int ktiles = K / BK;

    auto ldtile = [&](int kt) {
        const int k0 = kt * BK;
        #pragma unroll
        for (int p = 0; p < APASS; p++) {
            const int r = ar + p * ARPP;
            pa[p] = *(const float4*)(A + (size_t)(row0 + r) * lda + k0 + aq * 4);
        }
        #pragma unroll
        for (int p = 0; p < BPASS; p++) {
            const int n = ar + p * ARPP;
            if (n < N)
                pb[p] = *(const float4*)(W + (size_t)n * K + k0 + aq * 4);
            else
                pb[p] = make_float4(0.f, 0.f, 0.f, 0.f);
        }
    };
    auto sttile = [&]() {
        #pragma unroll
        for (int p = 0; p < APASS; p++) {
            const int r = ar + p * ARPP;
            float4 v;
            v.x = tf32_rna(pa[p].x); v.y = tf32_rna(pa[p].y);
            v.z = tf32_rna(pa[p].z); v.w = tf32_rna(pa[p].w);
            *(float4*)&As[r * BKp + aq * 4] = v;
        }
        #pragma unroll
        for (int p = 0; p < BPASS; p++) {
            const int n = ar + p * ARPP;
            float4 v;
            v.x = tf32_rna(pb[p].x); v.y = tf32_rna(pb[p].y);
            v.z = tf32_rna(pb[p].z); v.w = tf32_rna(pb[p].w);
            *(float4*)&Bs[n * BKp + aq * 4] = v;
        }
    };

    float acc[2][NT][4];
    #pragma unroll
    for (int mt = 0; mt < 2; mt++)
        #pragma unroll
        for (int nt = 0; nt < NT; nt++)
            #pragma unroll
            for (int i = 0; i < 4; i++) acc[mt][nt][i] = 0.f;

    ldtile(0);
    for (int kt = 0; kt < ktiles; kt++) {
        sttile();
        __syncthreads();
        if (kt + 1 < ktiles) ldtile(kt + 1);

        #pragma unroll
        for (int kk = 0; kk < BK / 8; kk++) {
            const int k = kk * 8;
            uint32_t a[2][4], bf[NT][2];
            #pragma unroll
            for (int mt = 0; mt < 2; mt++) {
                const int r = wm * 32 + mt * 16 + g;
                a[mt][0] = __float_as_uint(As[r * BKp + k + tq]);
                a[mt][1] = __float_as_uint(As[(r + 8) * BKp + k + tq]);
                a[mt][2] = __float_as_uint(As[r * BKp + k + tq + 4]);
                a[mt][3] = __float_as_uint(As[(r + 8) * BKp + k + tq + 4]);
            }
            #pragma unroll
            for (int nt = 0; nt < NT; nt++) {
                const int n = wn * (NT * 8) + nt * 8 + g;
                bf[nt][0] = __float_as_uint(Bs[n * BKp + k + tq]);
                bf[nt][1] = __float_as_uint(Bs[n * BKp + k + tq + 4]);
            }
            #pragma unroll
            for (int mt = 0; mt < 2; mt++)
                #pragma unroll
                for (int nt = 0; nt < NT; nt++) {
                    asm volatile(
                        "mma.sync.aligned.m16n8k8.row.col.f32.tf32.tf32.f32 "
                        "{%0,%1,%2,%3}, {%4,%5,%6,%7}, {%8,%9}, {%0,%1,%2,%3};"
                        : "+f"(acc[mt][nt][0]), "+f"(acc[mt][nt][1]),
                          "+f"(acc[mt][nt][2]), "+f"(acc[mt][nt][3])
                        : "r"(a[mt][0]), "r"(a[mt][1]), "r"(a[mt][2]), "r"(a[mt][3]),
                          "r"(bf[nt][0]), "r"(bf[nt][1]));
                }
        }
        __syncthreads();
    }

    // ---- epilogue: cols 16..47 -> global; cols 0..15 -> sdt ----
    #pragma unroll
    for (int mt = 0; mt < 2; mt++) {
        const int rl = wm * 32 + mt * 16 + g;       // local row 0..63
        const int r = row0 + rl;
        #pragma unroll
        for (int nt = 0; nt < NT; nt++) {
            const int c = wn * (NT * 8) + nt * 8 + 2 * tq;
            float2 v0, v1;
            v0.x = acc[mt][nt][0]; v0.y = acc[mt][nt][1];
            v1.x = acc[mt][nt][2]; v1.y = acc[mt][nt][3];
            if (c < 16) {
                *(float2*)&sdt[rl * 16 + c]       = v0;
                *(float2*)&sdt[(rl + 8) * 16 + c] = v1;
            } else if (c < N) {
                *(float2*)&xdb[(size_t)r * 48 + c] = v0;
                *(float2*)&xdb[(size_t)(r + 8) * 48 + c] = v1;
            }
        }
    }
    __syncthreads();

    // ---- dtproj phase: verbatim proven body, reading sdt instead of global ----
    const int dlane = tid & 31;
    #pragma unroll
    for (int rr = 0; rr < 8; rr++) {
        const int rl = (tid >> 5) * 8 + rr;          // local row 0..63
        const int r = row0 + rl;

        float4 dt0 = *(const float4*)&sdt[rl * 16 + 0];
        float4 dt1 = *(const float4*)&sdt[rl * 16 + 4];
        float4 dt2 = *(const float4*)&sdt[rl * 16 + 8];
        float4 dt3 = *(const float4*)&sdt[rl * 16 + 12];

        #pragma unroll
        for (int j = 0; j < 16; j++) {
            const int d = dlane + 32 * j;
            const float4* wr = (const float4*)&sw[d * 16];
            float4 w0 = wr[0], w1 = wr[1], w2 = wr[2], w3 = wr[3];
            float s = sb[d];
            s += dt0.x * w0.x + dt0.y * w0.y + dt0.z * w0.z + dt0.w * w0.w;
            s += dt1.x * w1.x + dt1.y * w1.y + dt1.z * w1.z + dt1.w * w1.w;
            s += dt2.x * w2.x + dt2.y * w2.y + dt2.z * w2.z + dt2.w * w2.w;
            s += dt3.x * w3.x + dt3.y * w3.y + dt3.z * w3.z + dt3.w * w3.w;
            delta[(size_t)r * 512 + d] = softplus_f(s);
        }
    }
}

// ---------------- input transpose: (B,C,L) -> (B*L, C), tf32-rounded ------------
__global__ __launch_bounds__(256)
void transpose_in_kernel(const float* __restrict__ in, float* __restrict__ out)
{
    __shared__ float t[32][33];
    const int b = blockIdx.z;
    const int c0 = blockIdx.y * 32, l0 = blockIdx.x * 32;
    for (int cc = threadIdx.y; cc < 32; cc += 8)
        t[cc][threadIdx.x] = in[((size_t)b * C_IN + c0 + cc) * LEN + l0 + threadIdx.x];
    __syncthreads();
    for (int ll = threadIdx.y; ll < 32; ll += 8)
        out[((size_t)b * LEN + l0 + ll) * C_IN + c0 + threadIdx.x] =
            tf32_rna(t[threadIdx.x][ll]);
}

// ---------------- depthwise causal conv + bias + silu (8 rows/thread) -----------
__global__ __launch_bounds__(256)
void conv_silu_kernel(const float* __restrict__ xz, const float* __restrict__ cw,
                      const float* __restrict__ cb, float* __restrict__ xc)
{
    const int i = blockIdx.x * 256 + threadIdx.x;
    const int d4 = (i & 127) * 4;
    const int r0 = (i >> 7) * 8;
    const int l0 = r0 & (LEN - 1);
    const float* p = xz + (size_t)r0 * 1024 + d4;

    const float4 z4 = make_float4(0.f, 0.f, 0.f, 0.f);
    float4 xr[11];
    xr[0] = (l0 >= 3) ? *(const float4*)(p - 3 * 1024) : z4;
    xr[1] = (l0 >= 2) ? *(const float4*)(p - 2 * 1024) : z4;
    xr[2] = (l0 >= 1) ? *(const float4*)(p - 1 * 1024) : z4;
    #pragma unroll
    for (int rr = 0; rr < 8; rr++)
        xr[3 + rr] = *(const float4*)(p + rr * 1024);

    const float4 wa = *(const float4*)(cw + (d4 + 0) * 4);
    const float4 wb = *(const float4*)(cw + (d4 + 1) * 4);
    const float4 wc = *(const float4*)(cw + (d4 + 2) * 4);
    const float4 wd = *(const float4*)(cw + (d4 + 3) * 4);
    const float4 bb = *(const float4*)(cb + d4);

    #pragma unroll
    for (int rr = 0; rr < 8; rr++) {
        const float4 t0 = xr[rr], t1 = xr[rr + 1], t2 = xr[rr + 2], t3 = xr[rr + 3];
        float4 acc;
        acc.x = bb.x + t0.x * wa.x + t1.x * wa.y + t2.x * wa.z + t3.x * wa.w;
        acc.y = bb.y + t0.y * wb.x + t1.y * wb.y + t2.y * wb.z + t3.y * wb.w;
        acc.z = bb.z + t0.z * wc.x + t1.z * wc.y + t2.z * wc.z + t3.z * wc.w;
        acc.w = bb.w + t0.w * wd.x + t1.w * wd.y + t2.w * wd.z + t3.w * wd.w;
        acc.x = silu_f(acc.x); acc.y = silu_f(acc.y);
        acc.z = silu_f(acc.z); acc.w = silu_f(acc.w);
        *(float4*)(xc + (size_t)(r0 + rr) * 512 + d4) = acc;
    }
}

// ---------------- scan pass 1: per-chunk summaries with smem staging -------------
__global__ __launch_bounds__(256)
void scan_pass1_kernel(const float* __restrict__ delta, const float* __restrict__ xc,
                       const float* __restrict__ xdb, const float* __restrict__ A_log,
                       float* __restrict__ esum, float* __restrict__ hend)
{
    __shared__ float sd[2][32][32], su[2][32][32];
    __shared__ float sB[2][32][16];

    const int b  = blockIdx.y;
    const int chunk = blockIdx.z;
    const int d0 = blockIdx.x * 32;
    const int tid = threadIdx.x;
    const int dl = tid >> 3, sl = tid & 7;
    const int d = d0 + dl;
    const int s0 = sl * 2;

    const float LOG2E = 1.4426950408889634f;
    const float a0L2 = -__expf(A_log[d * 16 + s0]) * LOG2E;
    const float a1L2 = -__expf(A_log[d * 16 + s0 + 1]) * LOG2E;

    const size_t rowbase = (size_t)b * LEN + (size_t)chunk * CLEN;

    float4 pd, pxc, pbc;
    auto prefetch = [&](int c) {
        const int l0 = c * 32;
        const int l = tid >> 3, q = tid & 7;
        const size_t r = rowbase + l0 + l;
        pd  = *(const float4*)(delta + r * 512 + d0 + q * 4);
        pxc = *(const float4*)(xc + r * 512 + d0 + q * 4);
        if (tid < 128) {
            const int l2 = tid >> 2, q2 = tid & 3;
            const size_t r2 = rowbase + l0 + l2;
            pbc = *(const float4*)(xdb + r2 * 48 + 16 + q2 * 4);
        }
    };
    auto sto = [&](int buf) {
        const int l = tid >> 3, q = tid & 7;
        *(float4*)&sd[buf][l][q * 4] = pd;
        float4 u;
        u.x = pd.x * pxc.x; u.y = pd.y * pxc.y;
        u.z = pd.z * pxc.z; u.w = pd.w * pxc.w;
        *(float4*)&su[buf][l][q * 4] = u;
        if (tid < 128) {
            const int l2 = tid >> 2, q2 = tid & 3;
            *(float4*)&sB[buf][l2][q2 * 4] = pbc;
        }
    };

    float h0 = 0.f, h1 = 0.f, E0 = 1.f, E1 = 1.f;
    prefetch(0);
    sto(0);
    __syncthreads();

    const int NCH = CLEN / 32;   // 4
    for (int c = 0; c < NCH; c++) {
        const int buf = c & 1;
        if (c + 1 < NCH) prefetch(c + 1);

        #pragma unroll 8
        for (int l = 0; l < 32; l++) {
            const float dt = sd[buf][l][dl];
            const float uv = su[buf][l][dl];
            const float2 Bp = *(const float2*)&sB[buf][l][s0];
            float e0, e1;
            asm("ex2.approx.f32 %0, %1;" : "=f"(e0) : "f"(a0L2 * dt));
            asm("ex2.approx.f32 %0, %1;" : "=f"(e1) : "f"(a1L2 * dt));
            E0 *= e0; E1 *= e1;
            h0 = fmaf(e0, h0, uv * Bp.x);
            h1 = fmaf(e1, h1, uv * Bp.y);
        }
        if (c + 1 < NCH) sto(buf ^ 1);
        __syncthreads();
    }

    const size_t idx = (((size_t)b * NCHUNK + chunk) * 512 + d) * 16 + s0;
    *(float2*)&esum[idx] = make_float2(E0, E1);
    *(float2*)&hend[idx] = make_float2(h0, h1);
}

// ---------------- prefix fold: exclusive prefix of (E, hend) per (b,d,s) ---------
__global__ __launch_bounds__(256)
void scan_prefix_kernel(const float* __restrict__ esum, const float* __restrict__ hend,
                        float* __restrict__ hpre)
{
    const int gidx = blockIdx.x * 256 + threadIdx.x;    // 0..32767
    const int b = gidx >> 12;
    const int rem = gidx & 4095;
    const int d = rem >> 3;
    const int s0 = (rem & 7) * 2;

    float h0 = 0.f, h1 = 0.f;
    #pragma unroll
    for (int j = 0; j < NCHUNK; j++) {
        const size_t idx = (((size_t)b * NCHUNK + j) * 512 + d) * 16 + s0;
        *(float2*)&hpre[idx] = make_float2(h0, h1);
        const float2 E  = *(const float2*)&esum[idx];
        const float2 he = *(const float2*)&hend[idx];
        h0 = fmaf(E.x, h0, he.x);
        h1 = fmaf(E.y, h1, he.y);
    }
}

// ---------------- scan pass 2: per-chunk full scan, h_in from hpre ---------------
__global__ __launch_bounds__(256)
void scan_kernel(const float* __restrict__ delta, const float* __restrict__ xz,
                 const float* __restrict__ xc, const float* __restrict__ xdb,
                 const float* __restrict__ A_log, const float* __restrict__ Dp,
                 const float* __restrict__ hpre,
                 float* __restrict__ y)
{
    __shared__ float sd[2][32][32], su[2][32][32];
    __shared__ float sB[2][32][16], sC[2][32][16];
    __shared__ float ys[32][32];

    const int b  = blockIdx.y;
    const int chunk = blockIdx.z;
    const int d0 = blockIdx.x * 32;
    const int tid = threadIdx.x;
    const int dl = tid >> 3, sl = tid & 7;
    const int d = d0 + dl;
    const int s0 = sl * 2;

    const float LOG2E = 1.4426950408889634f;
    const float a0L2 = -__expf(A_log[d * 16 + s0]) * LOG2E;
    const float a1L2 = -__expf(A_log[d * 16 + s0 + 1]) * LOG2E;

    const int el = tid >> 3;
    const int eq = (tid & 7) * 4;
    const float4 Dv4 = *(const float4*)(Dp + d0 + eq);

    const size_t rowbase = (size_t)b * LEN + (size_t)chunk * CLEN;

    const size_t pidx = (((size_t)b * NCHUNK + chunk) * 512 + d) * 16 + s0;
    const float2 hin = *(const float2*)&hpre[pidx];
    float h0 = hin.x, h1 = hin.y;

    float4 pd, pxc, pbc;
    float4 exc0, exc1;
    auto prefetch = [&](int c) {
        const int l0 = c * 32;
        const int l = tid >> 3, q = tid & 7;
        const size_t r = rowbase + l0 + l;
        pd  = *(const float4*)(delta + r * 512 + d0 + q * 4);
        pxc = *(const float4*)(xc + r * 512 + d0 + q * 4);
        const int j = tid & 127;
        const int l2 = j >> 2, q2 = j & 3;
        const size_t r2 = rowbase + l0 + l2;
        const int off = (tid < 128) ? 16 : 32;
        pbc = *(const float4*)(xdb + r2 * 48 + off + q2 * 4);
    };
    auto sto = [&](int buf) {
        const int l = tid >> 3, q = tid & 7;
        *(float4*)&sd[buf][l][q * 4] = pd;
        float4 u;
        u.x = pd.x * pxc.x; u.y = pd.y * pxc.y;
        u.z = pd.z * pxc.z; u.w = pd.w * pxc.w;
        *(float4*)&su[buf][l][q * 4] = u;
        if (buf == 0) exc0 = pxc; else exc1 = pxc;
        const int j = tid & 127;
        const int l2 = j >> 2, q2 = j & 3;
        if (tid < 128) *(float4*)&sB[buf][l2][q2 * 4] = pbc;
        else           *(float4*)&sC[buf][l2][q2 * 4] = pbc;
    };

    prefetch(0);
    sto(0);
    __syncthreads();

    const int NCH = CLEN / 32;   // 4
    for (int c = 0; c < NCH; c++) {
        const int buf = c & 1;
        if (c + 1 < NCH) prefetch(c + 1);

        const size_t erow = rowbase + c * 32 + el;
        const float4 pze = *(const float4*)(xz + erow * 1024 + 512 + d0 + eq);

        #pragma unroll 8
        for (int l = 0; l < 32; l++) {
            const float dt = sd[buf][l][dl];
            const float uv = su[buf][l][dl];
            const float2 Bp = *(const float2*)&sB[buf][l][s0];
            const float2 Cp = *(const float2*)&sC[buf][l][s0];
            float e0, e1;
            asm("ex2.approx.f32 %0, %1;" : "=f"(e0) : "f"(a0L2 * dt));
            asm("ex2.approx.f32 %0, %1;" : "=f"(e1) : "f"(a1L2 * dt));
            h0 = fmaf(e0, h0, uv * Bp.x);
            h1 = fmaf(e1, h1, uv * Bp.y);
            float p = fmaf(h1, Cp.y, h0 * Cp.x);
            p += __shfl_xor_sync(0xffffffffu, p, 4);
            p += __shfl_xor_sync(0xffffffffu, p, 2);
            p += __shfl_xor_sync(0xffffffffu, p, 1);
            if (sl == 0) ys[l][dl] = p;
        }
        __syncthreads();

        {
            const float4 pxe = (buf == 0) ? exc0 : exc1;
            float4 yv = *(const float4*)&ys[el][eq];
            float4 o;
            o.x = tf32_rna((yv.x + pxe.x * Dv4.x) * silu_f(pze.x));
            o.y = tf32_rna((yv.y + pxe.y * Dv4.y) * silu_f(pze.y));
            o.z = tf32_rna((yv.z + pxe.z * Dv4.z) * silu_f(pze.z));
            o.w = tf32_rna((yv.w + pxe.w * Dv4.w) * silu_f(pze.w));
            *(float4*)(y + erow * 512 + d0 + eq) = o;
        }
        if (c + 1 < NCH) sto(buf ^ 1);
        __syncthreads();
    }
}

// ---------------- host ----------------
extern "C" void kernel_launch(void* const* d_in, const int* in_sizes, int n_in,
                              void* d_out, int out_size)
{
    (void)in_sizes; (void)n_in; (void)out_size;
    const float* input      = (const float*)d_in[0];
    const float* in_proj_w  = (const float*)d_in[1];
    const float* conv_w     = (const float*)d_in[2];
    const float* conv_b     = (const float*)d_in[3];
    const float* x_proj_w   = (const float*)d_in[4];
    const float* dt_proj_w  = (const float*)d_in[5];
    const float* dt_proj_b  = (const float*)d_in[6];
    const float* A_log      = (const float*)d_in[7];
    const float* Dw         = (const float*)d_in[8];
    const float* out_proj_w = (const float*)d_in[9];
    const float* out_lin_w  = (const float*)d_in[10];
    const float* out_lin_b  = (const float*)d_in[11];
    float* out = (float*)d_out;

    float *px, *pxz, *pxc, *pxdb, *pdelta, *py, *pwt, *pes, *phe, *php;
    cudaGetSymbolAddress((void**)&px,     g_x);
    cudaGetSymbolAddress((void**)&pxz,    g_xz);
    cudaGetSymbolAddress((void**)&pxc,    g_xc);
    cudaGetSymbolAddress((void**)&pxdb,   g_xdb);
    cudaGetSymbolAddress((void**)&pdelta, g_delta);
    cudaGetSymbolAddress((void**)&py,     g_y);
    cudaGetSymbolAddress((void**)&pwt,    g_wt);
    cudaGetSymbolAddress((void**)&pes,    g_esum);
    cudaGetSymbolAddress((void**)&phe,    g_hend);
    cudaGetSymbolAddress((void**)&php,    g_hpre);

    float* wt_in  = pwt;
    float* wt_out = pwt + 2 * 262144;
    float* wt_lin = pwt + 2 * 262144 + 2 * 131072;

    const int PIPE_SMEM = 3 * 8192 * 4;      // 98304 bytes
    cudaFuncSetAttribute(gemm_pipe_kernel<0, false>,
                         cudaFuncAttributeMaxDynamicSharedMemorySize, PIPE_SMEM);
    cudaFuncSetAttribute(gemm_pipe_kernel<0, true>,
                         cudaFuncAttributeMaxDynamicSharedMemorySize, PIPE_SMEM);
    cudaFuncSetAttribute(gemm_pipe_kernel<3, false>,
                         cudaFuncAttributeMaxDynamicSharedMemorySize, PIPE_SMEM);

    const int XP_SMEM = (64 * 36 * 2 + 8192 + 512 + 64 * 16) * 4;   // 57344 bytes
    cudaFuncSetAttribute(xproj_dtproj_kernel,
                         cudaFuncAttributeMaxDynamicSharedMemorySize, XP_SMEM);

    cvt_all_kernel<<<(917504 / 4) / 256, 256>>>(in_proj_w, out_proj_w, out_lin_w, pwt);
    transpose_in_kernel<<<dim3(LEN / 32, C_IN / 32, BATCH), dim3(32, 8)>>>(input, px);

    for (int layer = 0; layer < 2; layer++) {
        const float* w_in   = wt_in  + (size_t)layer * 262144;
        const float* w_cv   = conv_w     + (size_t)layer * 512 * 4;
        const float* b_cv   = conv_b     + (size_t)layer * 512;
        const float* w_xp   = x_proj_w   + (size_t)layer * 48 * 512;
        const float* w_dt   = dt_proj_w  + (size_t)layer * 512 * 16;
        const float* b_dt   = dt_proj_b  + (size_t)layer * 512;
        const float* alog   = A_log      + (size_t)layer * 512 * 16;
        const float* dvec   = Dw         + (size_t)layer * 512;
        const float* w_out  = wt_out + (size_t)layer * 131072;

        // in_proj: (N=1024, K=256)
        gemm_pipe_kernel<0, false><<<dim3(8, NROWS / 128), 256, PIPE_SMEM>>>(
            px, C_IN, w_in, nullptr, pxz, 1024, 256);

        // conv (8 rows/thread)
        conv_silu_kernel<<<(NROWS / 8 * 128) / 256, 256>>>(pxz, w_cv, b_cv, pxc);

        // FUSED x_proj (N=48, K=512) + dt_proj
        xproj_dtproj_kernel<<<dim3(1, NROWS / 64), 256, XP_SMEM>>>(
            pxc, 512, w_xp, w_dt, b_dt, pxdb, pdelta, 48, 512);

        // chunked parallel scan (NCHUNK=16) + prefix precompute
        scan_pass1_kernel<<<dim3(16, BATCH, NCHUNK), 256>>>(
            pdelta, pxc, pxdb, alog, pes, phe);
        scan_prefix_kernel<<<128, 256>>>(pes, phe, php);
        scan_kernel<<<dim3(16, BATCH, NCHUNK), 256>>>(
            pdelta, pxz, pxc, pxdb, alog, dvec, php, py);

        // out_proj: (N=256, K=512) -> px, rounded for next GEMM
        gemm_pipe_kernel<0, true><<<dim3(2, NROWS / 128), 256, PIPE_SMEM>>>(
            py, 512, w_out, nullptr, px, 256, 512);
    }

    // final linear + bias + relu + fused scatter to (2,B,256,L)
    gemm_pipe_kernel<3, false><<<dim3(4, NROWS / 128), 256, PIPE_SMEM>>>(
        px, C_IN, wt_lin, out_lin_b, out, 0, 256);
}

// round 17
// speedup vs baseline: 1.0255x; 1.0255x over previous
#include <cuda_runtime.h>
#include <cstdint>

// ---------------- problem constants ----------------
#define BATCH 8
#define C_IN 256
#define LEN 2048
#define D_INNER 512
#define DT_RANK 16
#define D_STATE 16
#define NROWS (BATCH * LEN)          // 16384
#define NCHUNK 16
#define CLEN (LEN / NCHUNK)          // 128

// ---------------- scratch buffers ----------------
__device__ float g_x[NROWS * C_IN];
__device__ float g_xz[NROWS * 1024];
__device__ float g_xc[NROWS * D_INNER];
__device__ float g_xdb[NROWS * 48];
__device__ float g_delta[NROWS * D_INNER];
__device__ float g_y[NROWS * D_INNER];
__device__ float g_esum[BATCH * NCHUNK * D_INNER * D_STATE];
__device__ float g_hend[BATCH * NCHUNK * D_INNER * D_STATE];
__device__ float g_hpre[BATCH * NCHUNK * D_INNER * D_STATE];
// tf32-rounded weight copies: in_proj(2x262144) | out_proj(2x131072) | out_lin(131072)
__device__ float g_wt[2 * 262144 + 2 * 131072 + 131072];

// ---------------- helpers ----------------
__device__ __forceinline__ uint32_t cvt_tf32(float x) {
    uint32_t y;
    asm("cvt.rna.tf32.f32 %0, %1;" : "=r"(y) : "f"(x));
    return y;
}
__device__ __forceinline__ float tf32_rna(float x) {
    return __uint_as_float(cvt_tf32(x));
}
__device__ __forceinline__ float silu_f(float v) {
    return v / (1.f + __expf(-v));
}
__device__ __forceinline__ float softplus_f(float v) {
    return fmaxf(v, 0.f) + log1pf(__expf(-fabsf(v)));
}

#define CP16(dst, src) \
    asm volatile("cp.async.cg.shared.global [%0], [%1], 16;\n" :: "r"(dst), "l"(src))

__device__ __forceinline__ void ldsm_x4(uint32_t& d0, uint32_t& d1,
                                        uint32_t& d2, uint32_t& d3, uint32_t addr) {
    asm volatile("ldmatrix.sync.aligned.m8n8.x4.shared.b16 {%0,%1,%2,%3}, [%4];"
                 : "=r"(d0), "=r"(d1), "=r"(d2), "=r"(d3) : "r"(addr));
}

// ============================================================================
// Pipelined tf32 GEMM — proven mainloop; bottom sync removed (validated).
// EPI: 0 = none, 2 = bias+relu, 3 = bias+relu+SCATTER to (2,B,256,L).
// ============================================================================
template<int EPI, bool ROUND_OUT>
__global__ __launch_bounds__(256, 2)
void gemm_pipe_kernel(const float* __restrict__ A, int lda,
                      const float* __restrict__ W,
                      const float* __restrict__ bias,
                      float* __restrict__ C, int ldc, int K)
{
    extern __shared__ float smem[];
    constexpr int STAGE_FLOATS = 8192;

    const int tid  = threadIdx.x;
    const int warp = tid >> 5, lane = tid & 31;
    const int wm = warp >> 2, wn = warp & 3;
    const int g = lane >> 2, tq = lane & 3;
    const int row0 = blockIdx.y * 128;
    const int col0 = blockIdx.x * 128;

    const int arow = tid >> 3;
    const int aj   = tid & 7;
    const uint32_t swz = (uint32_t)((aj ^ (arow & 7)) << 4);
    uint32_t sbase = (uint32_t)__cvta_generic_to_shared(smem);

    const float* gA0 = A + (size_t)(row0 + arow) * lda + aj * 4;
    const float* gB0 = W + (size_t)(col0 + arow) * K   + aj * 4;

    auto load_stage = [&](int kt, int s) {
        const float* ga = gA0 + kt * 32;
        const float* gb = gB0 + kt * 32;
        uint32_t da = sbase + (uint32_t)(s * STAGE_FLOATS + arow * 32) * 4 + swz;
        uint32_t db = da + 4096 * 4;
        #pragma unroll
        for (int p = 0; p < 4; p++) {
            CP16(da + p * 4096, ga + (size_t)p * 32 * lda);
            CP16(db + p * 4096, gb + (size_t)p * 32 * K);
        }
        asm volatile("cp.async.commit_group;\n");
    };

    const int lmat = lane >> 3, lr = lane & 7;
    const uint32_t rsw = (uint32_t)lr << 4;
    uint32_t aBase[4], bBase[2];
    #pragma unroll
    for (int mt = 0; mt < 4; mt++) {
        const int row = wm * 64 + mt * 16 + (lmat & 1) * 8 + lr;
        aBase[mt] = sbase + (uint32_t)row * 128;
    }
    const uint32_t ablk = (uint32_t)(lmat >> 1);
    #pragma unroll
    for (int nt2 = 0; nt2 < 2; nt2++) {
        const int row = wn * 32 + nt2 * 16 + (lmat >> 1) * 8 + lr;
        bBase[nt2] = sbase + 4096 * 4 + (uint32_t)row * 128;
    }
    const uint32_t bblk = (uint32_t)(lmat & 1);

    float acc[4][4][4];
    #pragma unroll
    for (int mt = 0; mt < 4; mt++)
        #pragma unroll
        for (int nt = 0; nt < 4; nt++)
            #pragma unroll
            for (int i = 0; i < 4; i++) acc[mt][nt][i] = 0.f;

    const int ktiles = K / 32;
    load_stage(0, 0);
    if (ktiles > 1) load_stage(1, 1);

    int scur = 0;
    for (int kt = 0; kt < ktiles; kt++) {
        if (kt < ktiles - 1) asm volatile("cp.async.wait_group 1;\n");
        else                 asm volatile("cp.async.wait_group 0;\n");
        __syncthreads();

        if (kt + 2 < ktiles) load_stage(kt + 2, (scur + 2) % 3);

        const uint32_t soff = (uint32_t)(scur * STAGE_FLOATS) * 4;

        #pragma unroll
        for (int kk = 0; kk < 4; kk++) {
            uint32_t a[4][4], b[4][2];
            #pragma unroll
            for (int mt = 0; mt < 4; mt++) {
                const uint32_t addr = aBase[mt] + soff +
                    ((((uint32_t)(2 * kk) + ablk) << 4) ^ rsw);
                ldsm_x4(a[mt][0], a[mt][1], a[mt][2], a[mt][3], addr);
            }
            #pragma unroll
            for (int nt2 = 0; nt2 < 2; nt2++) {
                const uint32_t addr = bBase[nt2] + soff +
                    ((((uint32_t)(2 * kk) + bblk) << 4) ^ rsw);
                ldsm_x4(b[2 * nt2][0], b[2 * nt2][1],
                        b[2 * nt2 + 1][0], b[2 * nt2 + 1][1], addr);
            }
            #pragma unroll
            for (int mt = 0; mt < 4; mt++)
                #pragma unroll
                for (int nt = 0; nt < 4; nt++) {
                    asm volatile(
                        "mma.sync.aligned.m16n8k8.row.col.f32.tf32.tf32.f32 "
                        "{%0,%1,%2,%3}, {%4,%5,%6,%7}, {%8,%9}, {%0,%1,%2,%3};"
                        : "+f"(acc[mt][nt][0]), "+f"(acc[mt][nt][1]),
                          "+f"(acc[mt][nt][2]), "+f"(acc[mt][nt][3])
                        : "r"(a[mt][0]), "r"(a[mt][1]), "r"(a[mt][2]), "r"(a[mt][3]),
                          "r"(b[nt][0]), "r"(b[nt][1]));
                }
        }
        scur = (scur == 2) ? 0 : scur + 1;
    }

    #pragma unroll
    for (int mt = 0; mt < 4; mt++) {
        const int r = row0 + wm * 64 + mt * 16 + g;
        #pragma unroll
        for (int nt = 0; nt < 4; nt++) {
            const int c = col0 + wn * 32 + nt * 8 + 2 * tq;
            float b0 = 0.f, b1 = 0.f;
            if (EPI >= 2) { b0 = bias[c]; b1 = bias[c + 1]; }
            float2 v0, v1;
            v0.x = acc[mt][nt][0]; v0.y = acc[mt][nt][1];
            v1.x = acc[mt][nt][2]; v1.y = acc[mt][nt][3];
            if (EPI >= 2) {
                v0.x = fmaxf(v0.x + b0, 0.f); v0.y = fmaxf(v0.y + b1, 0.f);
                v1.x = fmaxf(v1.x + b0, 0.f); v1.y = fmaxf(v1.y + b1, 0.f);
            }
            if (ROUND_OUT) {
                v0.x = tf32_rna(v0.x); v0.y = tf32_rna(v0.y);
                v1.x = tf32_rna(v1.x); v1.y = tf32_rna(v1.y);
            }
            if (EPI == 3) {
                const int bb = r >> 11;
                const int l  = r & 2047;
                const int c1 = c + 1;
                const size_t base0 = ((size_t)((c  >> 8) * BATCH + bb)) * (C_IN * LEN)
                                   + (size_t)(c  & 255) * LEN;
                const size_t base1 = ((size_t)((c1 >> 8) * BATCH + bb)) * (C_IN * LEN)
                                   + (size_t)(c1 & 255) * LEN;
                C[base0 + l]     = v0.x;
                C[base1 + l]     = v0.y;
                C[base0 + l + 8] = v1.x;
                C[base1 + l + 8] = v1.y;
            } else {
                *(float2*)&C[(size_t)r * ldc + c] = v0;
                *(float2*)&C[(size_t)(r + 8) * ldc + c] = v1;
            }
        }
    }
}

// ---------------- merged prologue: weight cvt (blocks 0..895) + input transpose --
// Block-range dispatch; both bodies identical to the proven separate kernels.
__global__ __launch_bounds__(256)
void prep_kernel(const float* __restrict__ w_in, const float* __restrict__ w_out,
                 const float* __restrict__ w_lin, float* __restrict__ dst,
                 const float* __restrict__ in, float* __restrict__ out)
{
    if (blockIdx.x < 896) {
        const int i = (blockIdx.x * 256 + threadIdx.x) * 4;   // over 917504 floats
        const float* src;
        int off;
        if (i < 524288)       { src = w_in;  off = i; }
        else if (i < 786432)  { src = w_out; off = i - 524288; }
        else                  { src = w_lin; off = i - 786432; }
        float4 v = *(const float4*)(src + off);
        v.x = tf32_rna(v.x); v.y = tf32_rna(v.y);
        v.z = tf32_rna(v.z); v.w = tf32_rna(v.w);
        *(float4*)(dst + i) = v;
    } else {
        __shared__ float t[32][33];
        const int bid = blockIdx.x - 896;           // 0..4095
        const int lb = bid & 63;                    // l-tile 0..63
        const int cb = (bid >> 6) & 7;              // c-tile 0..7
        const int b  = bid >> 9;                    // batch 0..7
        const int c0 = cb * 32, l0 = lb * 32;
        const int tx = threadIdx.x & 31, ty = threadIdx.x >> 5;
        for (int cc = ty; cc < 32; cc += 8)
            t[cc][tx] = in[((size_t)b * C_IN + c0 + cc) * LEN + l0 + tx];
        __syncthreads();
        for (int ll = ty; ll < 32; ll += 8)
            out[((size_t)b * LEN + l0 + ll) * C_IN + c0 + tx] =
                tf32_rna(t[tx][ll]);
    }
}

// ============================================================================
// Small tf32 GEMM (x_proj, N=48) — proven, unchanged
// ============================================================================
template<int BM, int BK, int EPI>
__global__ __launch_bounds__(256)
void gemm_tf32_kernel(const float* __restrict__ A, int lda,
                      const float* __restrict__ W,
                      const float* __restrict__ bias,
                      float* __restrict__ C, int ldc,
                      int N, int K)
{
    constexpr int BN = 64;
    constexpr int BKp = BK + 4;
    constexpr int WCOLS = 8 / (BM / 32);
    constexpr int NT = BN / (WCOLS * 8);
    __shared__ float As[BM][BKp];
    __shared__ float Bs[BN][BKp];

    const int tid  = threadIdx.x;
    const int warp = tid >> 5, lane = tid & 31;
    const int wm = warp / WCOLS, wn = warp % WCOLS;
    const int g = lane >> 2, tq = lane & 3;
    const int row0 = blockIdx.y * BM;
    const int col0 = blockIdx.x * BN;

    constexpr int AF4   = BK / 4;
    constexpr int ARPP  = 256 / AF4;
    constexpr int APASS = BM / ARPP;
    constexpr int BPASS = BN / ARPP;
    const int ar = tid / AF4;
    const int aq = tid % AF4;

    float4 pa[APASS], pb[BPASS > 0 ? BPASS : 1];
    const int ktiles = K / BK;

    auto ldtile = [&](int kt) {
        const int k0 = kt * BK;
        #pragma unroll
        for (int p = 0; p < APASS; p++) {
            const int r = ar + p * ARPP;
            pa[p] = *(const float4*)(A + (size_t)(row0 + r) * lda + k0 + aq * 4);
        }
        #pragma unroll
        for (int p = 0; p < BPASS; p++) {
            const int n = ar + p * ARPP;
            if (col0 + n < N)
                pb[p] = *(const float4*)(W + (size_t)(col0 + n) * K + k0 + aq * 4);
            else
                pb[p] = make_float4(0.f, 0.f, 0.f, 0.f);
        }
    };
    auto sttile = [&]() {
        #pragma unroll
        for (int p = 0; p < APASS; p++) {
            const int r = ar + p * ARPP;
            float4 v;
            v.x = tf32_rna(pa[p].x); v.y = tf32_rna(pa[p].y);
            v.z = tf32_rna(pa[p].z); v.w = tf32_rna(pa[p].w);
            *(float4*)&As[r][aq * 4] = v;
        }
        #pragma unroll
        for (int p = 0; p < BPASS; p++) {
            const int n = ar + p * ARPP;
            float4 v;
            v.x = tf32_rna(pb[p].x); v.y = tf32_rna(pb[p].y);
            v.z = tf32_rna(pb[p].z); v.w = tf32_rna(pb[p].w);
            *(float4*)&Bs[n][aq * 4] = v;
        }
    };

    float acc[2][NT][4];
    #pragma unroll
    for (int mt = 0; mt < 2; mt++)
        #pragma unroll
        for (int nt = 0; nt < NT; nt++)
            #pragma unroll
            for (int i = 0; i < 4; i++) acc[mt][nt][i] = 0.f;

    ldtile(0);
    for (int kt = 0; kt < ktiles; kt++) {
        sttile();
        __syncthreads();
        if (kt + 1 < ktiles) ldtile(kt + 1);

        #pragma unroll
        for (int kk = 0; kk < BK / 8; kk++) {
            const int k = kk * 8;
            uint32_t a[2][4], bf[NT][2];
            #pragma unroll
            for (int mt = 0; mt < 2; mt++) {
                const int r = wm * 32 + mt * 16 + g;
                a[mt][0] = __float_as_uint(As[r][k + tq]);
                a[mt][1] = __float_as_uint(As[r + 8][k + tq]);
                a[mt][2] = __float_as_uint(As[r][k + tq + 4]);
                a[mt][3] = __float_as_uint(As[r + 8][k + tq + 4]);
            }
            #pragma unroll
            for (int nt = 0; nt < NT; nt++) {
                const int n = wn * (NT * 8) + nt * 8 + g;
                bf[nt][0] = __float_as_uint(Bs[n][k + tq]);
                bf[nt][1] = __float_as_uint(Bs[n][k + tq + 4]);
            }
            #pragma unroll
            for (int mt = 0; mt < 2; mt++)
                #pragma unroll
                for (int nt = 0; nt < NT; nt++) {
                    asm volatile(
                        "mma.sync.aligned.m16n8k8.row.col.f32.tf32.tf32.f32 "
                        "{%0,%1,%2,%3}, {%4,%5,%6,%7}, {%8,%9}, {%0,%1,%2,%3};"
                        : "+f"(acc[mt][nt][0]), "+f"(acc[mt][nt][1]),
                          "+f"(acc[mt][nt][2]), "+f"(acc[mt][nt][3])
                        : "r"(a[mt][0]), "r"(a[mt][1]), "r"(a[mt][2]), "r"(a[mt][3]),
                          "r"(bf[nt][0]), "r"(bf[nt][1]));
                }
        }
        __syncthreads();
    }

    #pragma unroll
    for (int mt = 0; mt < 2; mt++) {
        const int r = row0 + wm * 32 + mt * 16 + g;
        #pragma unroll
        for (int nt = 0; nt < NT; nt++) {
            const int c = col0 + wn * (NT * 8) + nt * 8 + 2 * tq;
            if (c < N) {
                float2 v0, v1;
                v0.x = acc[mt][nt][0]; v0.y = acc[mt][nt][1];
                v1.x = acc[mt][nt][2]; v1.y = acc[mt][nt][3];
                *(float2*)&C[(size_t)r * ldc + c] = v0;
                *(float2*)&C[(size_t)(r + 8) * ldc + c] = v1;
            }
        }
    }
}

// ---------------- dt_proj: exact fp32, 64 rows/block ----------------
__global__ __launch_bounds__(256)
void dtproj_kernel(const float* __restrict__ xdb, const float* __restrict__ w,
                   const float* __restrict__ bias, float* __restrict__ out)
{
    __shared__ float sw[512 * 16];
    __shared__ float sb[512];
    const int tid = threadIdx.x;
    #pragma unroll
    for (int i = 0; i < 8; i++)
        *(float4*)&sw[(i * 256 + tid) * 4] = *(const float4*)(w + (i * 256 + tid) * 4);
    sb[tid] = bias[tid];
    sb[tid + 256] = bias[tid + 256];
    __syncthreads();

    const int dlane = tid & 31;
    #pragma unroll
    for (int rr = 0; rr < 8; rr++) {
        const int r = blockIdx.x * 64 + (tid >> 5) * 8 + rr;

        float4 dt0 = *(const float4*)(xdb + (size_t)r * 48 + 0);
        float4 dt1 = *(const float4*)(xdb + (size_t)r * 48 + 4);
        float4 dt2 = *(const float4*)(xdb + (size_t)r * 48 + 8);
        float4 dt3 = *(const float4*)(xdb + (size_t)r * 48 + 12);

        #pragma unroll
        for (int j = 0; j < 16; j++) {
            const int d = dlane + 32 * j;
            const float4* wr = (const float4*)&sw[d * 16];
            float4 w0 = wr[0], w1 = wr[1], w2 = wr[2], w3 = wr[3];
            float s = sb[d];
            s += dt0.x * w0.x + dt0.y * w0.y + dt0.z * w0.z + dt0.w * w0.w;
            s += dt1.x * w1.x + dt1.y * w1.y + dt1.z * w1.z + dt1.w * w1.w;
            s += dt2.x * w2.x + dt2.y * w2.y + dt2.z * w2.z + dt2.w * w2.w;
            s += dt3.x * w3.x + dt3.y * w3.y + dt3.z * w3.z + dt3.w * w3.w;
            out[(size_t)r * 512 + d] = softplus_f(s);
        }
    }
}

// ---------------- depthwise causal conv + bias + silu (8 rows/thread) -----------
__global__ __launch_bounds__(256)
void conv_silu_kernel(const float* __restrict__ xz, const float* __restrict__ cw,
                      const float* __restrict__ cb, float* __restrict__ xc)
{
    const int i = blockIdx.x * 256 + threadIdx.x;
    const int d4 = (i & 127) * 4;
    const int r0 = (i >> 7) * 8;
    const int l0 = r0 & (LEN - 1);
    const float* p = xz + (size_t)r0 * 1024 + d4;

    const float4 z4 = make_float4(0.f, 0.f, 0.f, 0.f);
    float4 xr[11];
    xr[0] = (l0 >= 3) ? *(const float4*)(p - 3 * 1024) : z4;
    xr[1] = (l0 >= 2) ? *(const float4*)(p - 2 * 1024) : z4;
    xr[2] = (l0 >= 1) ? *(const float4*)(p - 1 * 1024) : z4;
    #pragma unroll
    for (int rr = 0; rr < 8; rr++)
        xr[3 + rr] = *(const float4*)(p + rr * 1024);

    const float4 wa = *(const float4*)(cw + (d4 + 0) * 4);
    const float4 wb = *(const float4*)(cw + (d4 + 1) * 4);
    const float4 wc = *(const float4*)(cw + (d4 + 2) * 4);
    const float4 wd = *(const float4*)(cw + (d4 + 3) * 4);
    const float4 bb = *(const float4*)(cb + d4);

    #pragma unroll
    for (int rr = 0; rr < 8; rr++) {
        const float4 t0 = xr[rr], t1 = xr[rr + 1], t2 = xr[rr + 2], t3 = xr[rr + 3];
        float4 acc;
        acc.x = bb.x + t0.x * wa.x + t1.x * wa.y + t2.x * wa.z + t3.x * wa.w;
        acc.y = bb.y + t0.y * wb.x + t1.y * wb.y + t2.y * wb.z + t3.y * wb.w;
        acc.z = bb.z + t0.z * wc.x + t1.z * wc.y + t2.z * wc.z + t3.z * wc.w;
        acc.w = bb.w + t0.w * wd.x + t1.w * wd.y + t2.w * wd.z + t3.w * wd.w;
        acc.x = silu_f(acc.x); acc.y = silu_f(acc.y);
        acc.z = silu_f(acc.z); acc.w = silu_f(acc.w);
        *(float4*)(xc + (size_t)(r0 + rr) * 512 + d4) = acc;
    }
}

// ---------------- scan pass 1: per-chunk summaries with smem staging -------------
__global__ __launch_bounds__(256)
void scan_pass1_kernel(const float* __restrict__ delta, const float* __restrict__ xc,
                       const float* __restrict__ xdb, const float* __restrict__ A_log,
                       float* __restrict__ esum, float* __restrict__ hend)
{
    __shared__ float sd[2][32][32], su[2][32][32];
    __shared__ float sB[2][32][16];

    const int b  = blockIdx.y;
    const int chunk = blockIdx.z;
    const int d0 = blockIdx.x * 32;
    const int tid = threadIdx.x;
    const int dl = tid >> 3, sl = tid & 7;
    const int d = d0 + dl;
    const int s0 = sl * 2;

    const float LOG2E = 1.4426950408889634f;
    const float a0L2 = -__expf(A_log[d * 16 + s0]) * LOG2E;
    const float a1L2 = -__expf(A_log[d * 16 + s0 + 1]) * LOG2E;

    const size_t rowbase = (size_t)b * LEN + (size_t)chunk * CLEN;

    float4 pd, pxc, pbc;
    auto prefetch = [&](int c) {
        const int l0 = c * 32;
        const int l = tid >> 3, q = tid & 7;
        const size_t r = rowbase + l0 + l;
        pd  = *(const float4*)(delta + r * 512 + d0 + q * 4);
        pxc = *(const float4*)(xc + r * 512 + d0 + q * 4);
        if (tid < 128) {
            const int l2 = tid >> 2, q2 = tid & 3;
            const size_t r2 = rowbase + l0 + l2;
            pbc = *(const float4*)(xdb + r2 * 48 + 16 + q2 * 4);
        }
    };
    auto sto = [&](int buf) {
        const int l = tid >> 3, q = tid & 7;
        *(float4*)&sd[buf][l][q * 4] = pd;
        float4 u;
        u.x = pd.x * pxc.x; u.y = pd.y * pxc.y;
        u.z = pd.z * pxc.z; u.w = pd.w * pxc.w;
        *(float4*)&su[buf][l][q * 4] = u;
        if (tid < 128) {
            const int l2 = tid >> 2, q2 = tid & 3;
            *(float4*)&sB[buf][l2][q2 * 4] = pbc;
        }
    };

    float h0 = 0.f, h1 = 0.f, E0 = 1.f, E1 = 1.f;
    prefetch(0);
    sto(0);
    __syncthreads();

    const int NCH = CLEN / 32;   // 4
    for (int c = 0; c < NCH; c++) {
        const int buf = c & 1;
        if (c + 1 < NCH) prefetch(c + 1);

        #pragma unroll 8
        for (int l = 0; l < 32; l++) {
            const float dt = sd[buf][l][dl];
            const float uv = su[buf][l][dl];
            const float2 Bp = *(const float2*)&sB[buf][l][s0];
            float e0, e1;
            asm("ex2.approx.f32 %0, %1;" : "=f"(e0) : "f"(a0L2 * dt));
            asm("ex2.approx.f32 %0, %1;" : "=f"(e1) : "f"(a1L2 * dt));
            E0 *= e0; E1 *= e1;
            h0 = fmaf(e0, h0, uv * Bp.x);
            h1 = fmaf(e1, h1, uv * Bp.y);
        }
        if (c + 1 < NCH) sto(buf ^ 1);
        __syncthreads();
    }

    const size_t idx = (((size_t)b * NCHUNK + chunk) * 512 + d) * 16 + s0;
    *(float2*)&esum[idx] = make_float2(E0, E1);
    *(float2*)&hend[idx] = make_float2(h0, h1);
}

// ---------------- prefix fold: exclusive prefix of (E, hend) per (b,d,s) ---------
__global__ __launch_bounds__(256)
void scan_prefix_kernel(const float* __restrict__ esum, const float* __restrict__ hend,
                        float* __restrict__ hpre)
{
    const int gidx = blockIdx.x * 256 + threadIdx.x;    // 0..32767
    const int b = gidx >> 12;
    const int rem = gidx & 4095;
    const int d = rem >> 3;
    const int s0 = (rem & 7) * 2;

    float h0 = 0.f, h1 = 0.f;
    #pragma unroll
    for (int j = 0; j < NCHUNK; j++) {
        const size_t idx = (((size_t)b * NCHUNK + j) * 512 + d) * 16 + s0;
        *(float2*)&hpre[idx] = make_float2(h0, h1);
        const float2 E  = *(const float2*)&esum[idx];
        const float2 he = *(const float2*)&hend[idx];
        h0 = fmaf(E.x, h0, he.x);
        h1 = fmaf(E.y, h1, he.y);
    }
}

// ---------------- scan pass 2: per-chunk full scan, h_in from hpre ---------------
__global__ __launch_bounds__(256)
void scan_kernel(const float* __restrict__ delta, const float* __restrict__ xz,
                 const float* __restrict__ xc, const float* __restrict__ xdb,
                 const float* __restrict__ A_log, const float* __restrict__ Dp,
                 const float* __restrict__ hpre,
                 float* __restrict__ y)
{
    __shared__ float sd[2][32][32], su[2][32][32];
    __shared__ float sB[2][32][16], sC[2][32][16];
    __shared__ float ys[32][32];

    const int b  = blockIdx.y;
    const int chunk = blockIdx.z;
    const int d0 = blockIdx.x * 32;
    const int tid = threadIdx.x;
    const int dl = tid >> 3, sl = tid & 7;
    const int d = d0 + dl;
    const int s0 = sl * 2;

    const float LOG2E = 1.4426950408889634f;
    const float a0L2 = -__expf(A_log[d * 16 + s0]) * LOG2E;
    const float a1L2 = -__expf(A_log[d * 16 + s0 + 1]) * LOG2E;

    const int el = tid >> 3;
    const int eq = (tid & 7) * 4;
    const float4 Dv4 = *(const float4*)(Dp + d0 + eq);

    const size_t rowbase = (size_t)b * LEN + (size_t)chunk * CLEN;

    const size_t pidx = (((size_t)b * NCHUNK + chunk) * 512 + d) * 16 + s0;
    const float2 hin = *(const float2*)&hpre[pidx];
    float h0 = hin.x, h1 = hin.y;

    float4 pd, pxc, pbc;
    float4 exc0, exc1;
    auto prefetch = [&](int c) {
        const int l0 = c * 32;
        const int l = tid >> 3, q = tid & 7;
        const size_t r = rowbase + l0 + l;
        pd  = *(const float4*)(delta + r * 512 + d0 + q * 4);
        pxc = *(const float4*)(xc + r * 512 + d0 + q * 4);
        const int j = tid & 127;
        const int l2 = j >> 2, q2 = j & 3;
        const size_t r2 = rowbase + l0 + l2;
        const int off = (tid < 128) ? 16 : 32;
        pbc = *(const float4*)(xdb + r2 * 48 + off + q2 * 4);
    };
    auto sto = [&](int buf) {
        const int l = tid >> 3, q = tid & 7;
        *(float4*)&sd[buf][l][q * 4] = pd;
        float4 u;
        u.x = pd.x * pxc.x; u.y = pd.y * pxc.y;
        u.z = pd.z * pxc.z; u.w = pd.w * pxc.w;
        *(float4*)&su[buf][l][q * 4] = u;
        if (buf == 0) exc0 = pxc; else exc1 = pxc;
        const int j = tid & 127;
        const int l2 = j >> 2, q2 = j & 3;
        if (tid < 128) *(float4*)&sB[buf][l2][q2 * 4] = pbc;
        else           *(float4*)&sC[buf][l2][q2 * 4] = pbc;
    };

    prefetch(0);
    sto(0);
    __syncthreads();

    const int NCH = CLEN / 32;   // 4
    for (int c = 0; c < NCH; c++) {
        const int buf = c & 1;
        if (c + 1 < NCH) prefetch(c + 1);

        const size_t erow = rowbase + c * 32 + el;
        const float4 pze = *(const float4*)(xz + erow * 1024 + 512 + d0 + eq);

        #pragma unroll 8
        for (int l = 0; l < 32; l++) {
            const float dt = sd[buf][l][dl];
            const float uv = su[buf][l][dl];
            const float2 Bp = *(const float2*)&sB[buf][l][s0];
            const float2 Cp = *(const float2*)&sC[buf][l][s0];
            float e0, e1;
            asm("ex2.approx.f32 %0, %1;" : "=f"(e0) : "f"(a0L2 * dt));
            asm("ex2.approx.f32 %0, %1;" : "=f"(e1) : "f"(a1L2 * dt));
            h0 = fmaf(e0, h0, uv * Bp.x);
            h1 = fmaf(e1, h1, uv * Bp.y);
            float p = fmaf(h1, Cp.y, h0 * Cp.x);
            p += __shfl_xor_sync(0xffffffffu, p, 4);
            p += __shfl_xor_sync(0xffffffffu, p, 2);
            p += __shfl_xor_sync(0xffffffffu, p, 1);
            if (sl == 0) ys[l][dl] = p;
        }
        __syncthreads();

        {
            const float4 pxe = (buf == 0) ? exc0 : exc1;
            float4 yv = *(const float4*)&ys[el][eq];
            float4 o;
            o.x = tf32_rna((yv.x + pxe.x * Dv4.x) * silu_f(pze.x));
            o.y = tf32_rna((yv.y + pxe.y * Dv4.y) * silu_f(pze.y));
            o.z = tf32_rna((yv.z + pxe.z * Dv4.z) * silu_f(pze.z));
            o.w = tf32_rna((yv.w + pxe.w * Dv4.w) * silu_f(pze.w));
            *(float4*)(y + erow * 512 + d0 + eq) = o;
        }
        if (c + 1 < NCH) sto(buf ^ 1);
        __syncthreads();
    }
}

// ---------------- host ----------------
extern "C" void kernel_launch(void* const* d_in, const int* in_sizes, int n_in,
                              void* d_out, int out_size)
{
    (void)in_sizes; (void)n_in; (void)out_size;
    const float* input      = (const float*)d_in[0];
    const float* in_proj_w  = (const float*)d_in[1];
    const float* conv_w     = (const float*)d_in[2];
    const float* conv_b     = (const float*)d_in[3];
    const float* x_proj_w   = (const float*)d_in[4];
    const float* dt_proj_w  = (const float*)d_in[5];
    const float* dt_proj_b  = (const float*)d_in[6];
    const float* A_log      = (const float*)d_in[7];
    const float* Dw         = (const float*)d_in[8];
    const float* out_proj_w = (const float*)d_in[9];
    const float* out_lin_w  = (const float*)d_in[10];
    const float* out_lin_b  = (const float*)d_in[11];
    float* out = (float*)d_out;

    float *px, *pxz, *pxc, *pxdb, *pdelta, *py, *pwt, *pes, *phe, *php;
    cudaGetSymbolAddress((void**)&px,     g_x);
    cudaGetSymbolAddress((void**)&pxz,    g_xz);
    cudaGetSymbolAddress((void**)&pxc,    g_xc);
    cudaGetSymbolAddress((void**)&pxdb,   g_xdb);
    cudaGetSymbolAddress((void**)&pdelta, g_delta);
    cudaGetSymbolAddress((void**)&py,     g_y);
    cudaGetSymbolAddress((void**)&pwt,    g_wt);
    cudaGetSymbolAddress((void**)&pes,    g_esum);
    cudaGetSymbolAddress((void**)&phe,    g_hend);
    cudaGetSymbolAddress((void**)&php,    g_hpre);

    float* wt_in  = pwt;
    float* wt_out = pwt + 2 * 262144;
    float* wt_lin = pwt + 2 * 262144 + 2 * 131072;

    const int PIPE_SMEM = 3 * 8192 * 4;      // 98304 bytes
    cudaFuncSetAttribute(gemm_pipe_kernel<0, false>,
                         cudaFuncAttributeMaxDynamicSharedMemorySize, PIPE_SMEM);
    cudaFuncSetAttribute(gemm_pipe_kernel<0, true>,
                         cudaFuncAttributeMaxDynamicSharedMemorySize, PIPE_SMEM);
    cudaFuncSetAttribute(gemm_pipe_kernel<3, false>,
                         cudaFuncAttributeMaxDynamicSharedMemorySize, PIPE_SMEM);

    // merged prologue: weight cvt (896 blocks) + input transpose (4096 blocks)
    prep_kernel<<<896 + 4096, 256>>>(in_proj_w, out_proj_w, out_lin_w, pwt,
                                     input, px);

    for (int layer = 0; layer < 2; layer++) {
        const float* w_in   = wt_in  + (size_t)layer * 262144;
        const float* w_cv   = conv_w     + (size_t)layer * 512 * 4;
        const float* b_cv   = conv_b     + (size_t)layer * 512;
        const float* w_xp   = x_proj_w   + (size_t)layer * 48 * 512;
        const float* w_dt   = dt_proj_w  + (size_t)layer * 512 * 16;
        const float* b_dt   = dt_proj_b  + (size_t)layer * 512;
        const float* alog   = A_log      + (size_t)layer * 512 * 16;
        const float* dvec   = Dw         + (size_t)layer * 512;
        const float* w_out  = wt_out + (size_t)layer * 131072;

        // in_proj: (N=1024, K=256)
        gemm_pipe_kernel<0, false><<<dim3(8, NROWS / 128), 256, PIPE_SMEM>>>(
            px, C_IN, w_in, nullptr, pxz, 1024, 256);

        // conv (8 rows/thread)
        conv_silu_kernel<<<(NROWS / 8 * 128) / 256, 256>>>(pxz, w_cv, b_cv, pxc);

        // x_proj: (N=48, K=512)
        gemm_tf32_kernel<64, 32, 0><<<dim3(1, NROWS / 64), 256>>>(
            pxc, 512, w_xp, nullptr, pxdb, 48, 48, 512);

        dtproj_kernel<<<NROWS / 64, 256>>>(pxdb, w_dt, b_dt, pdelta);

        // chunked parallel scan (NCHUNK=16) + prefix precompute
        scan_pass1_kernel<<<dim3(16, BATCH, NCHUNK), 256>>>(
            pdelta, pxc, pxdb, alog, pes, phe);
        scan_prefix_kernel<<<128, 256>>>(pes, phe, php);
        scan_kernel<<<dim3(16, BATCH, NCHUNK), 256>>>(
            pdelta, pxz, pxc, pxdb, alog, dvec, php, py);

        // out_proj: (N=256, K=512) -> px, rounded for next GEMM
        gemm_pipe_kernel<0, true><<<dim3(2, NROWS / 128), 256, PIPE_SMEM>>>(
            py, 512, w_out, nullptr, px, 256, 512);
    }

    // final linear + bias + relu + fused scatter to (2,B,256,L)
    gemm_pipe_kernel<3, false><<<dim3(4, NROWS / 128), 256, PIPE_SMEM>>>(
        px, C_IN, wt_lin, out_lin_b, out, 0, 256);
}